// round 1
// baseline (speedup 1.0000x reference)
#include <cuda_runtime.h>

// Problem shape is fixed by the reference setup: N=16, C=3, H=512, W=512, patch=15.
#define N_    16
#define H_    512
#define W_    512
#define PLANE (H_ * W_)
#define PAD   7          // patch_size 15 -> pad 7

// Scratch: luv(input) - luv(target), horizontally box-filtered. 48 MB static.
__device__ float  g_scratch[(size_t)N_ * 3 * H_ * W_];
__device__ double g_accum[3];

__global__ void zero_accum_kernel() {
    if (threadIdx.x < 3) g_accum[threadIdx.x] = 0.0;
}

__device__ __forceinline__ float f_func(float t) {
    // matches reference: cbrt(t) if t > 0.008856 else 7.787*t + 16/116
    return (t > 0.008856f) ? cbrtf(t) : fmaf(7.787f, t, 16.0f / 116.0f);
}

__device__ __forceinline__ void rgb_to_luv(float r, float g, float b,
                                           float& l, float& u, float& v) {
    float x = 0.4124564f * r + 0.3575761f * g + 0.1804375f * b;
    float y = 0.2126729f * r + 0.7151522f * g + 0.0721750f * b;
    float z = 0.0193339f * r + 0.1191920f * g + 0.9503041f * b;
    x *= (1.0f / 0.95047f);
    z *= (1.0f / 1.08883f);
    float fx = f_func(x);
    float fy = f_func(y);
    float fz = f_func(z);
    l = 116.0f * fy - 16.0f;
    u = 13.0f * l * (fx - fy);
    v = 13.0f * l * (fy - fz);
}

// Pass 1: one block per (n, h) row. Compute luv diff, horizontal 15-tap box
// (zero padding), write to scratch in the same NCHW layout.
__global__ void __launch_bounds__(W_) luv_diff_hbox_kernel(
    const float* __restrict__ in, const float* __restrict__ tgt) {
    __shared__ float sl[W_];
    __shared__ float su[W_];
    __shared__ float sv[W_];

    int nh = blockIdx.x;          // [0, N*H)
    int n  = nh / H_;
    int h  = nh - n * H_;
    int w  = threadIdx.x;

    size_t base = ((size_t)(n * 3) * H_ + h) * W_ + w;  // channel 0 plane

    float r0 = in[base],  g0 = in[base + PLANE],  b0 = in[base + 2 * (size_t)PLANE];
    float r1 = tgt[base], g1 = tgt[base + PLANE], b1 = tgt[base + 2 * (size_t)PLANE];

    float l0, u0, v0, l1, u1, v1;
    rgb_to_luv(r0, g0, b0, l0, u0, v0);
    rgb_to_luv(r1, g1, b1, l1, u1, v1);

    sl[w] = l0 - l1;
    su[w] = u0 - u1;
    sv[w] = v0 - v1;
    __syncthreads();

    float al = 0.f, au = 0.f, av = 0.f;
#pragma unroll
    for (int k = -PAD; k <= PAD; k++) {
        int x = w + k;
        if (x >= 0 && x < W_) {
            al += sl[x];
            au += su[x];
            av += sv[x];
        }
    }

    g_scratch[base]                      = al;
    g_scratch[base + PLANE]              = au;
    g_scratch[base + 2 * (size_t)PLANE]  = av;
}

// Pass 2: vertical 15-tap box (sliding window down column chunks), square,
// reduce. Each thread owns one (n, c, w, chunk-of-128-rows).
#define CHUNK   128
#define NCHUNK  (H_ / CHUNK)   // 4
#define V_TPB   256

__global__ void __launch_bounds__(V_TPB) vbox_reduce_kernel() {
    int g     = blockIdx.x * V_TPB + threadIdx.x;
    int w     = g & (W_ - 1);
    int rest  = g >> 9;              // W_ = 512 = 2^9
    int chunk = rest & (NCHUNK - 1);
    int col   = rest >> 2;           // n*3 + c, in [0, 48)
    int c     = col % 3;

    const float* d = g_scratch + (size_t)col * PLANE + w;
    int h0 = chunk * CHUNK;

    float sum = 0.f;
#pragma unroll
    for (int k = -PAD; k <= PAD; k++) {
        int hh = h0 + k;
        if (hh >= 0 && hh < H_) sum += d[(size_t)hh * W_];
    }

    float acc = 0.f;
#pragma unroll 4
    for (int h = h0; h < h0 + CHUNK; ++h) {
        acc = fmaf(sum, sum, acc);
        int   add = h + PAD + 1;
        int   rem = h - PAD;
        float va  = (add < H_)  ? d[(size_t)add * W_] : 0.f;
        float vr  = (rem >= 0)  ? d[(size_t)rem * W_] : 0.f;
        sum += va - vr;
    }

    // All threads in a block share the same channel c (block spans w only).
    __shared__ float red[V_TPB];
    red[threadIdx.x] = acc;
    __syncthreads();
#pragma unroll
    for (int s = V_TPB / 2; s > 0; s >>= 1) {
        if (threadIdx.x < s) red[threadIdx.x] += red[threadIdx.x + s];
        __syncthreads();
    }
    if (threadIdx.x == 0) atomicAdd(&g_accum[c], (double)red[0]);
}

__global__ void finalize_kernel(float* __restrict__ out) {
    double total = g_accum[0] + g_accum[1] + g_accum[2];
    out[0] = (float)(total / (double)((size_t)N_ * PLANE));
}

extern "C" void kernel_launch(void* const* d_in, const int* in_sizes, int n_in,
                              void* d_out, int out_size) {
    const float* in  = (const float*)d_in[0];
    const float* tgt = (const float*)d_in[1];
    float* out = (float*)d_out;

    zero_accum_kernel<<<1, 32>>>();
    luv_diff_hbox_kernel<<<N_ * H_, W_>>>(in, tgt);
    vbox_reduce_kernel<<<(N_ * 3 * W_ * NCHUNK) / V_TPB, V_TPB>>>();
    finalize_kernel<<<1, 1>>>(out);
}

// round 2
// speedup vs baseline: 1.1390x; 1.1390x over previous
#include <cuda_runtime.h>

// Shape fixed by reference setup: N=16, C=3, H=512, W=512, patch=15.
#define N_      16
#define H_      512
#define W_      512
#define PLANE   (H_ * W_)
#define PAD     7
#define TAPS    15
#define STRIPS  8
#define STRIP_H (H_ / STRIPS)   // 64
#define TPB     512

#define SD_W (W_ + 14)   // diff row, 7 zero-pad each side
#define SP_W (W_ + 10)   // p5 partial row, indices 0..521

__device__ double g_accum[3];

__global__ void zero_accum_kernel() {
    if (threadIdx.x < 3) g_accum[threadIdx.x] = 0.0;
}

__device__ __forceinline__ float f_func(float t) {
    // reference: cbrt(t) if t > 0.008856 else 7.787*t + 16/116
    // fast cbrt via MUFU.LG2 + FMUL + MUFU.EX2 (rel err ~5e-7)
    float cb = __powf(t, 1.0f / 3.0f);
    return (t > 0.008856f) ? cb : fmaf(7.787f, t, 16.0f / 116.0f);
}

__device__ __forceinline__ void rgb_to_luv(float r, float g, float b,
                                           float& l, float& u, float& v) {
    float x = 0.4124564f * r + 0.3575761f * g + 0.1804375f * b;
    float y = 0.2126729f * r + 0.7151522f * g + 0.0721750f * b;
    float z = 0.0193339f * r + 0.1191920f * g + 0.9503041f * b;
    x *= (1.0f / 0.95047f);
    z *= (1.0f / 1.08883f);
    float fx = f_func(x);
    float fy = f_func(y);
    float fz = f_func(z);
    l = 116.0f * fy - 16.0f;
    u = 13.0f * l * (fx - fy);
    v = 13.0f * l * (fy - fz);
}

// Fused: luv-diff -> horizontal 15-box (two-level 5+5+5) -> vertical 15-box
// (running sum + 15-row shared ring) -> square -> reduce. No global scratch.
__global__ void __launch_bounds__(TPB) fused_kernel(
    const float* __restrict__ in, const float* __restrict__ tgt) {
    extern __shared__ float sm[];
    float* ring = sm;                     // [3][TAPS][W_]  hbox rows
    float* sd   = ring + 3 * TAPS * W_;   // [3][SD_W]      padded diff row
    float* sp   = sd + 3 * SD_W;          // [3][SP_W]      p5 partials

    const int t     = threadIdx.x;
    const int n     = blockIdx.x >> 3;        // image
    const int strip = blockIdx.x & (STRIPS - 1);
    const int h0    = strip * STRIP_H;

    // Zero ring: thread t writes exactly the w==t entries (i % 512 == t),
    // so no barrier needed for ring correctness.
    for (int i = t; i < 3 * TAPS * W_; i += TPB) ring[i] = 0.f;
    // Zero sd pads (stay zero forever; interior writes cover [7, 518]).
    if (t < 14) {
        int idx = (t < 7) ? t : (W_ + 7 + (t - 7));
        sd[idx] = 0.f; sd[SD_W + idx] = 0.f; sd[2 * SD_W + idx] = 0.f;
    }

    float vs0 = 0.f, vs1 = 0.f, vs2 = 0.f;   // vertical running sums
    float ac0 = 0.f, ac1 = 0.f, ac2 = 0.f;   // sum of squares

    const size_t base_n = (size_t)n * 3 * PLANE + t;

    for (int iter = 0; iter < STRIP_H + 14; ++iter) {
        const int hr = h0 - PAD + iter;      // input row being ingested
        float d0 = 0.f, d1 = 0.f, d2 = 0.f;
        if (hr >= 0 && hr < H_) {
            size_t off = base_n + (size_t)hr * W_;
            float r0 = in[off],  g0 = in[off + PLANE],  b0 = in[off + 2 * PLANE];
            float r1 = tgt[off], g1 = tgt[off + PLANE], b1 = tgt[off + 2 * PLANE];
            float l0, u0, v0, l1, u1, v1;
            rgb_to_luv(r0, g0, b0, l0, u0, v0);
            rgb_to_luv(r1, g1, b1, l1, u1, v1);
            d0 = l0 - l1; d1 = u0 - u1; d2 = v0 - v1;
        }
        sd[7 + t] = d0; sd[SD_W + 7 + t] = d1; sd[2 * SD_W + 7 + t] = d2;
        __syncthreads();   // sd writes visible; prior iter's sp reads done

        // p5(j) = sum of 5 consecutive padded diffs starting at j
        {
            float a0 = 0.f, a1 = 0.f, a2 = 0.f;
            #pragma unroll
            for (int i = 0; i < 5; i++) {
                a0 += sd[t + i];
                a1 += sd[SD_W + t + i];
                a2 += sd[2 * SD_W + t + i];
            }
            sp[t] = a0; sp[SP_W + t] = a1; sp[2 * SP_W + t] = a2;
            if (t < 10) {
                int j = W_ + t;
                float b0 = 0.f, b1 = 0.f, b2 = 0.f;
                #pragma unroll
                for (int i = 0; i < 5; i++) {
                    b0 += sd[j + i];
                    b1 += sd[SD_W + j + i];
                    b2 += sd[2 * SD_W + j + i];
                }
                sp[j] = b0; sp[SP_W + j] = b1; sp[2 * SP_W + j] = b2;
            }
        }
        __syncthreads();   // sp writes visible; prior p5 reads of sd done

        // 15-tap hbox = p5(w) + p5(w+5) + p5(w+10)
        float hb0 = sp[t] + sp[t + 5] + sp[t + 10];
        float hb1 = sp[SP_W + t] + sp[SP_W + t + 5] + sp[SP_W + t + 10];
        float hb2 = sp[2 * SP_W + t] + sp[2 * SP_W + t + 5] + sp[2 * SP_W + t + 10];

        // vertical sliding window via ring (each thread touches only w==t)
        int slot = iter % TAPS;
        float* r0p = ring + (size_t)slot * W_ + t;
        float* r1p = ring + (size_t)(TAPS + slot) * W_ + t;
        float* r2p = ring + (size_t)(2 * TAPS + slot) * W_ + t;
        vs0 += hb0 - *r0p; *r0p = hb0;
        vs1 += hb1 - *r1p; *r1p = hb1;
        vs2 += hb2 - *r2p; *r2p = hb2;

        if (iter >= 14) {   // output row h = h0 + iter - 14 is complete
            ac0 = fmaf(vs0, vs0, ac0);
            ac1 = fmaf(vs1, vs1, ac1);
            ac2 = fmaf(vs2, vs2, ac2);
        }
    }

    // Block reduction: warp shuffle, then 16 partials per channel in shared.
    #pragma unroll
    for (int o = 16; o > 0; o >>= 1) {
        ac0 += __shfl_down_sync(0xffffffffu, ac0, o);
        ac1 += __shfl_down_sync(0xffffffffu, ac1, o);
        ac2 += __shfl_down_sync(0xffffffffu, ac2, o);
    }
    __syncthreads();                     // done with sd; reuse as scratch
    float* red = sd;
    int wid = t >> 5, lane = t & 31;
    if (lane == 0) {
        red[wid] = ac0; red[16 + wid] = ac1; red[32 + wid] = ac2;
    }
    __syncthreads();
    if (t < 3) {
        float s = 0.f;
        #pragma unroll
        for (int i = 0; i < 16; i++) s += red[t * 16 + i];
        atomicAdd(&g_accum[t], (double)s);
    }
}

__global__ void finalize_kernel(float* __restrict__ out) {
    double total = g_accum[0] + g_accum[1] + g_accum[2];
    out[0] = (float)(total / (double)((size_t)N_ * PLANE));
}

extern "C" void kernel_launch(void* const* d_in, const int* in_sizes, int n_in,
                              void* d_out, int out_size) {
    const float* in  = (const float*)d_in[0];
    const float* tgt = (const float*)d_in[1];
    float* out = (float*)d_out;

    const int smem_bytes = (3 * TAPS * W_ + 3 * SD_W + 3 * SP_W) * (int)sizeof(float);
    cudaFuncSetAttribute(fused_kernel,
                         cudaFuncAttributeMaxDynamicSharedMemorySize, smem_bytes);

    zero_accum_kernel<<<1, 32>>>();
    fused_kernel<<<N_ * STRIPS, TPB, smem_bytes>>>(in, tgt);
    finalize_kernel<<<1, 1>>>(out);
}

// round 3
// speedup vs baseline: 1.6170x; 1.4197x over previous
#include <cuda_runtime.h>
#include <cuda_fp16.h>

// Shape fixed by reference setup: N=16, C=3, H=512, W=512, patch=15.
#define N_      16
#define H_      512
#define W_      512
#define PLANE   (H_ * W_)
#define PAD     7
#define TAPS    15
#define STRIPS  16
#define STRIP_H (H_ / STRIPS)        // 32
#define ITERS   (STRIP_H + 14)       // 46
#define TPB     512
#define NBLK    (N_ * STRIPS)        // 256

#define SD_W (W_ + 14)   // padded diff row
#define SP_W (W_ + 10)   // p5 partial row

__device__ double g_accum[3];
__device__ int    g_done = 0;

__device__ __forceinline__ float f_func(float t) {
    // reference: cbrt(t) if t > 0.008856 else 7.787*t + 16/116
    float cb = __powf(t, 1.0f / 3.0f);        // MUFU.LG2 + FMUL + MUFU.EX2
    return (t > 0.008856f) ? cb : fmaf(7.787f, t, 16.0f / 116.0f);
}

__device__ __forceinline__ void rgb_to_luv(float r, float g, float b,
                                           float& l, float& u, float& v) {
    float x = 0.4124564f * r + 0.3575761f * g + 0.1804375f * b;
    float y = 0.2126729f * r + 0.7151522f * g + 0.0721750f * b;
    float z = 0.0193339f * r + 0.1191920f * g + 0.9503041f * b;
    x *= (1.0f / 0.95047f);
    z *= (1.0f / 1.08883f);
    float fx = f_func(x);
    float fy = f_func(y);
    float fz = f_func(z);
    l = 116.0f * fy - 16.0f;
    u = 13.0f * l * (fx - fy);
    v = 13.0f * l * (fy - fz);
}

__device__ __forceinline__ void load_row(const float* __restrict__ in,
                                         const float* __restrict__ tgt,
                                         size_t base_n, int hr, float* p) {
    if (hr >= 0 && hr < H_) {
        size_t off = base_n + (size_t)hr * W_;
        p[0] = in[off];  p[1] = in[off + PLANE];  p[2] = in[off + 2 * PLANE];
        p[3] = tgt[off]; p[4] = tgt[off + PLANE]; p[5] = tgt[off + 2 * PLANE];
    } else {
        p[0] = p[1] = p[2] = p[3] = p[4] = p[5] = 0.f;
    }
}

// Fully fused: luv-diff -> hbox 15 (5+5+5) -> vbox 15 (running sum, fp16 ring)
// -> square -> block reduce -> atomics -> last block finalizes + resets state.
__global__ void __launch_bounds__(TPB, 2) fused_kernel(
    const float* __restrict__ in, const float* __restrict__ tgt,
    float* __restrict__ out) {
    extern __shared__ char smraw[];
    __half* ring = (__half*)smraw;                       // [3][TAPS][W_]
    float*  sd   = (float*)(smraw + 3 * TAPS * W_ * 2);  // [3][SD_W]
    float*  sp   = sd + 3 * SD_W;                        // [3][SP_W]

    const int t     = threadIdx.x;
    const int n     = blockIdx.x >> 4;
    const int strip = blockIdx.x & (STRIPS - 1);
    const int h0    = strip * STRIP_H;

    // Zero ring (thread t owns w==t slots -> no barrier needed before use).
    const __half hz = __float2half(0.f);
    for (int i = t; i < 3 * TAPS * W_; i += TPB) ring[i] = hz;
    // Zero sd pads (stay zero forever).
    if (t < 14) {
        int idx = (t < 7) ? t : (W_ + 7 + (t - 7));
        sd[idx] = 0.f; sd[SD_W + idx] = 0.f; sd[2 * SD_W + idx] = 0.f;
    }

    float vs0 = 0.f, vs1 = 0.f, vs2 = 0.f;
    float ac0 = 0.f, ac1 = 0.f, ac2 = 0.f;

    const size_t base_n = (size_t)n * 3 * PLANE + t;

    float cur[6], nxt[6];
    load_row(in, tgt, base_n, h0 - PAD, cur);

    for (int iter = 0; iter < ITERS; ++iter) {
        // Prefetch next row while this row runs through smem/barrier phases.
        if (iter + 1 < ITERS)
            load_row(in, tgt, base_n, h0 - PAD + iter + 1, nxt);

        float l0, u0, v0, l1, u1, v1;
        rgb_to_luv(cur[0], cur[1], cur[2], l0, u0, v0);
        rgb_to_luv(cur[3], cur[4], cur[5], l1, u1, v1);

        sd[7 + t]            = l0 - l1;
        sd[SD_W + 7 + t]     = u0 - u1;
        sd[2 * SD_W + 7 + t] = v0 - v1;
        __syncthreads();

        // p5(j) = sum of 5 consecutive padded diffs
        {
            float a0 = 0.f, a1 = 0.f, a2 = 0.f;
            #pragma unroll
            for (int i = 0; i < 5; i++) {
                a0 += sd[t + i];
                a1 += sd[SD_W + t + i];
                a2 += sd[2 * SD_W + t + i];
            }
            sp[t] = a0; sp[SP_W + t] = a1; sp[2 * SP_W + t] = a2;
            if (t < 10) {
                int j = W_ + t;
                float b0 = 0.f, b1 = 0.f, b2 = 0.f;
                #pragma unroll
                for (int i = 0; i < 5; i++) {
                    b0 += sd[j + i];
                    b1 += sd[SD_W + j + i];
                    b2 += sd[2 * SD_W + j + i];
                }
                sp[j] = b0; sp[SP_W + j] = b1; sp[2 * SP_W + j] = b2;
            }
        }
        __syncthreads();

        // 15-tap hbox, rounded once to fp16; the SAME rounded value is added
        // to and later subtracted from vs -> exact cancellation, no drift.
        __half h0h = __float2half(sp[t] + sp[t + 5] + sp[t + 10]);
        __half h1h = __float2half(sp[SP_W + t] + sp[SP_W + t + 5] + sp[SP_W + t + 10]);
        __half h2h = __float2half(sp[2 * SP_W + t] + sp[2 * SP_W + t + 5] + sp[2 * SP_W + t + 10]);

        int slot = iter % TAPS;
        __half* r0p = ring + (size_t)slot * W_ + t;
        __half* r1p = ring + (size_t)(TAPS + slot) * W_ + t;
        __half* r2p = ring + (size_t)(2 * TAPS + slot) * W_ + t;
        vs0 += __half2float(h0h) - __half2float(*r0p); *r0p = h0h;
        vs1 += __half2float(h1h) - __half2float(*r1p); *r1p = h1h;
        vs2 += __half2float(h2h) - __half2float(*r2p); *r2p = h2h;

        if (iter >= 14) {
            ac0 = fmaf(vs0, vs0, ac0);
            ac1 = fmaf(vs1, vs1, ac1);
            ac2 = fmaf(vs2, vs2, ac2);
        }

        #pragma unroll
        for (int i = 0; i < 6; i++) cur[i] = nxt[i];
    }

    // Block reduction
    #pragma unroll
    for (int o = 16; o > 0; o >>= 1) {
        ac0 += __shfl_down_sync(0xffffffffu, ac0, o);
        ac1 += __shfl_down_sync(0xffffffffu, ac1, o);
        ac2 += __shfl_down_sync(0xffffffffu, ac2, o);
    }
    __syncthreads();
    float* red = sd;
    int wid = t >> 5, lane = t & 31;
    if (lane == 0) {
        red[wid] = ac0; red[16 + wid] = ac1; red[32 + wid] = ac2;
    }
    __syncthreads();
    if (t < 3) {
        float s = 0.f;
        #pragma unroll
        for (int i = 0; i < 16; i++) s += red[t * 16 + i];
        atomicAdd(&g_accum[t], (double)s);
    }
    __threadfence();
    __syncthreads();

    // Last block finalizes and resets global state (graph-replay safe).
    __shared__ int is_last;
    if (t == 0) is_last = (atomicAdd(&g_done, 1) == NBLK - 1);
    __syncthreads();
    if (is_last && t == 0) {
        double total = g_accum[0] + g_accum[1] + g_accum[2];
        out[0] = (float)(total / (double)((size_t)N_ * PLANE));
        g_accum[0] = 0.0; g_accum[1] = 0.0; g_accum[2] = 0.0;
        g_done = 0;
    }
}

extern "C" void kernel_launch(void* const* d_in, const int* in_sizes, int n_in,
                              void* d_out, int out_size) {
    const float* in  = (const float*)d_in[0];
    const float* tgt = (const float*)d_in[1];
    float* out = (float*)d_out;

    const int smem_bytes = 3 * TAPS * W_ * 2                 // fp16 ring
                         + (3 * SD_W + 3 * SP_W) * (int)sizeof(float);
    cudaFuncSetAttribute(fused_kernel,
                         cudaFuncAttributeMaxDynamicSharedMemorySize, smem_bytes);

    fused_kernel<<<NBLK, TPB, smem_bytes>>>(in, tgt, out);
}

// round 5
// speedup vs baseline: 2.2625x; 1.3992x over previous
#include <cuda_runtime.h>
#include <cuda_fp16.h>

// Shape fixed by reference setup: N=16, C=3, H=512, W=512, patch=15.
#define N_       16
#define H_       512
#define W_       512
#define PLANE    (H_ * W_)
#define STRIPS   16
#define STRIP_H  32
#define TPB      512
#define NBLK     (N_ * STRIPS)      // 256
#define ITERS    12                 // groups of 4 rows covering h0-8 .. h0+39
#define RSLOT    16                 // fp16 ring slots (power of 2)
#define SD_STRIDE 532               // 8 pad + 512 + 12 pad
#define S4_STRIDE 132               // 2 pad + 128 + 2 pad
#define RING_ELEMS (RSLOT * 3 * W_) // 24576 halves = 48 KB
#define SMEM_BYTES (RING_ELEMS * 2 + 12 * SD_STRIDE * 4 + 12 * S4_STRIDE * 4)

__device__ double g_accum[3];
__device__ int    g_done = 0;

__device__ __forceinline__ float f_func(float t) {
    // reference: cbrt(t) if t > 0.008856 else 7.787*t + 16/116
    float cb = __powf(t, 1.0f / 3.0f);     // MUFU.LG2 + FMUL + MUFU.EX2
    return (t > 0.008856f) ? cb : fmaf(7.787f, t, 16.0f / 116.0f);
}

struct F3 { float l, u, v; };

__device__ __forceinline__ F3 rgb2luv(float r, float g, float b) {
    float x = 0.4124564f * r + 0.3575761f * g + 0.1804375f * b;
    float y = 0.2126729f * r + 0.7151522f * g + 0.0721750f * b;
    float z = 0.0193339f * r + 0.1191920f * g + 0.9503041f * b;
    x *= (1.0f / 0.95047f);
    z *= (1.0f / 1.08883f);
    float fx = f_func(x);
    float fy = f_func(y);
    float fz = f_func(z);
    F3 o;
    o.l = 116.0f * fy - 16.0f;
    o.u = 13.0f * o.l * (fx - fy);
    o.v = 13.0f * o.l * (fy - fz);
    return o;
}

// Fully fused, 4-rows-per-iteration:
//  A: vectorized loads + luv-diff (4 px/thread) -> per-ty sd/s4; read ring olds
//  B: horizontal 15-box via block-sum + increments -> fp16 ring
//  C: vertical 15-box running sum per column + square + accumulate
__global__ void __launch_bounds__(TPB, 2) fused_kernel(
    const float* __restrict__ in, const float* __restrict__ tgt,
    float* __restrict__ out) {
    extern __shared__ char smraw[];
    __half* ring = (__half*)smraw;                       // [RSLOT][3][W_]
    float*  sd   = (float*)(smraw + RING_ELEMS * 2);     // [4][3][SD_STRIDE]
    float*  s4   = sd + 12 * SD_STRIDE;                  // [4][3][S4_STRIDE]

    const int t  = threadIdx.x;
    const int tx = t & 127;
    const int ty = t >> 7;
    const int n     = blockIdx.x >> 4;
    const int strip = blockIdx.x & 15;
    const int h0    = strip * STRIP_H;

    // Init: ring zero (thread t owns linear idx % 512 == column t).
    const __half hz = __float2half(0.f);
    for (int i = t; i < RING_ELEMS; i += TPB) ring[i] = hz;
    // Zero sd pads for all 12 planes: 8 left + 12 right per plane = 240 slots.
    if (t < 240) {
        int p = t / 20, k = t % 20;
        int j = (k < 8) ? k : (512 + k);          // 0..7 or 520..531
        sd[p * SD_STRIDE + j] = 0.f;
    }
    // Zero s4 pads: 2 left + 2 right per plane = 48 slots.
    if (t < 48) {
        int p = t / 4, k = t % 4;
        int j = (k < 2) ? k : (128 + k);          // 0,1 or 130,131
        s4[p * S4_STRIDE + j] = 0.f;
    }
    __syncthreads();

    const float4* inA = (const float4*)in;
    const float4* inB = (const float4*)tgt;
    const int P4    = PLANE / 4;                 // 65536
    const int base4 = n * 3 * P4 + tx;

    float* sdt = sd + ty * 3 * SD_STRIDE;        // this thread's row buffers
    float* s4t = s4 + ty * 3 * S4_STRIDE;

    float vs0 = 0.f, vs1 = 0.f, vs2 = 0.f;
    float ac0 = 0.f, ac1 = 0.f, ac2 = 0.f;

    for (int it = 0; it < ITERS; ++it) {
        const int gb = h0 - 8 + 4 * it;
        const int hr = gb + ty;

        // ---- phase A: load 4 rows, luv-diff, store sd/s4; read ring olds ----
        float4 d0 = {0.f, 0.f, 0.f, 0.f}, d1 = d0, d2 = d0;
        if (hr >= h0 - 7 && hr <= h0 + 38 && hr >= 0 && hr < H_) {
            int rb = base4 + hr * (W_ / 4);
            float4 ra = inA[rb], ga = inA[rb + P4], ba = inA[rb + 2 * P4];
            float4 rc = inB[rb], gc = inB[rb + P4], bc = inB[rb + 2 * P4];
            #define LANE(c) { F3 A = rgb2luv(ra.c, ga.c, ba.c); \
                              F3 B = rgb2luv(rc.c, gc.c, bc.c); \
                              d0.c = A.l - B.l; d1.c = A.u - B.u; d2.c = A.v - B.v; }
            LANE(x) LANE(y) LANE(z) LANE(w)
            #undef LANE
        }
        *(float4*)&sdt[8 + 4 * tx]                 = d0;
        *(float4*)&sdt[SD_STRIDE + 8 + 4 * tx]     = d1;
        *(float4*)&sdt[2 * SD_STRIDE + 8 + 4 * tx] = d2;
        s4t[2 + tx]                  = d0.x + d0.y + d0.z + d0.w;
        s4t[S4_STRIDE + 2 + tx]      = d1.x + d1.y + d1.z + d1.w;
        s4t[2 * S4_STRIDE + 2 + tx]  = d2.x + d2.y + d2.z + d2.w;

        // Evicted (old) ring values for rows gb..gb+3: hb[r-15] lives at slot
        // (r+1)&15 and will be (partially) overwritten in phase B, so read it
        // here, before the barrier.
        float old0[4], old1[4], old2[4];
        #pragma unroll
        for (int j = 0; j < 4; j++) {
            const __half* rp = ring + ((gb + 1 + j) & 15) * (3 * W_) + t;
            old0[j] = __half2float(rp[0]);
            old1[j] = __half2float(rp[W_]);
            old2[j] = __half2float(rp[2 * W_]);
        }
        __syncthreads();

        // ---- phase B: 15-tap hbox for row gb+ty, pixels 4tx..4tx+3 ----
        {
            __half* wr = ring + ((gb + ty) & 15) * (3 * W_);
            #pragma unroll
            for (int ch = 0; ch < 3; ch++) {
                const float* sdc = sdt + ch * SD_STRIDE;
                const float* s4c = s4t + ch * S4_STRIDE;
                float s0 = s4c[tx] + s4c[tx + 1] + s4c[tx + 2] + s4c[tx + 3];
                float4 dL = *(const float4*)&sdc[4 * tx];        // d[4tx-8..4tx-5]
                float4 dR = *(const float4*)&sdc[16 + 4 * tx];   // d[4tx+8..4tx+11]
                float hb0 = s0 - dL.x;
                float hb1 = hb0 + dR.x - dL.y;
                float hb2 = hb1 + dR.y - dL.z;
                float hb3 = hb2 + dR.z - dL.w;
                __half2* wp = (__half2*)(wr + ch * W_ + 4 * tx);
                wp[0] = __floats2half2_rn(hb0, hb1);
                wp[1] = __floats2half2_rn(hb2, hb3);
            }
        }
        __syncthreads();

        // ---- phase C: vertical running sum for column t, 4 new rows ----
        #pragma unroll
        for (int j = 0; j < 4; j++) {
            const int r = gb + j;
            const __half* rp = ring + (r & 15) * (3 * W_) + t;
            vs0 += __half2float(rp[0])      - old0[j];
            vs1 += __half2float(rp[W_])     - old1[j];
            vs2 += __half2float(rp[2 * W_]) - old2[j];
            if (r >= h0 + 7 && r <= h0 + 38) {   // output row r-7 in strip
                ac0 = fmaf(vs0, vs0, ac0);
                ac1 = fmaf(vs1, vs1, ac1);
                ac2 = fmaf(vs2, vs2, ac2);
            }
        }
    }

    // ---- block reduction ----
    #pragma unroll
    for (int o = 16; o > 0; o >>= 1) {
        ac0 += __shfl_down_sync(0xffffffffu, ac0, o);
        ac1 += __shfl_down_sync(0xffffffffu, ac1, o);
        ac2 += __shfl_down_sync(0xffffffffu, ac2, o);
    }
    __syncthreads();
    float* red = sd;                               // reuse smem
    int wid = t >> 5, lane = t & 31;
    if (lane == 0) { red[wid] = ac0; red[16 + wid] = ac1; red[32 + wid] = ac2; }
    __syncthreads();
    if (t < 3) {
        float s = 0.f;
        #pragma unroll
        for (int i = 0; i < 16; i++) s += red[t * 16 + i];
        atomicAdd(&g_accum[t], (double)s);
    }
    __threadfence();
    __syncthreads();

    // Last block finalizes and resets global state (graph-replay safe).
    __shared__ int is_last;
    if (t == 0) is_last = (atomicAdd(&g_done, 1) == NBLK - 1);
    __syncthreads();
    if (is_last && t == 0) {
        double total = g_accum[0] + g_accum[1] + g_accum[2];
        out[0] = (float)(total / (double)((size_t)N_ * PLANE));
        g_accum[0] = 0.0; g_accum[1] = 0.0; g_accum[2] = 0.0;
        g_done = 0;
    }
}

extern "C" void kernel_launch(void* const* d_in, const int* in_sizes, int n_in,
                              void* d_out, int out_size) {
    const float* in  = (const float*)d_in[0];
    const float* tgt = (const float*)d_in[1];
    float* out = (float*)d_out;

    cudaFuncSetAttribute(fused_kernel,
                         cudaFuncAttributeMaxDynamicSharedMemorySize, SMEM_BYTES);
    fused_kernel<<<NBLK, TPB, SMEM_BYTES>>>(in, tgt, out);
}

// round 6
// speedup vs baseline: 2.3483x; 1.0379x over previous
#include <cuda_runtime.h>
#include <cuda_fp16.h>

// Shape fixed by reference setup: N=16, C=3, H=512, W=512, patch=15.
#define N_       16
#define H_       512
#define W_       512
#define PLANE    (H_ * W_)
#define STRIPS   16
#define STRIP_H  32
#define TPB      512
#define NBLK     (N_ * STRIPS)      // 256
#define ITERS    12                 // 4-row groups covering h0-8 .. h0+39
#define RSLOT    16                 // ring slots (power of 2)
#define SD_STRIDE 532               // 8 pad + 512 + 12 pad
#define S4_STRIDE 132               // 2 pad + 128 + 2 pad
// Ring: [RSLOT][W_] of uint2 {half2(l,u), half2(v,pad)} = 64 KB
#define RING_U2   (RSLOT * W_)
#define SMEM_BYTES (RING_U2 * 8 + 12 * SD_STRIDE * 4 + 12 * S4_STRIDE * 4)

__device__ double g_accum[3];
__device__ int    g_done = 0;

__device__ __forceinline__ float f_func(float t) {
    // reference: cbrt(t) if t > 0.008856 else 7.787*t + 16/116
    float cb = __powf(t, 1.0f / 3.0f);     // MUFU.LG2 + FMUL + MUFU.EX2
    return (t > 0.008856f) ? cb : fmaf(7.787f, t, 16.0f / 116.0f);
}

struct F3 { float l, u, v; };

__device__ __forceinline__ F3 rgb2luv(float r, float g, float b) {
    float x = 0.4124564f * r + 0.3575761f * g + 0.1804375f * b;
    float y = 0.2126729f * r + 0.7151522f * g + 0.0721750f * b;
    float z = 0.0193339f * r + 0.1191920f * g + 0.9503041f * b;
    x *= (1.0f / 0.95047f);
    z *= (1.0f / 1.08883f);
    float fx = f_func(x);
    float fy = f_func(y);
    float fz = f_func(z);
    F3 o;
    o.l = 116.0f * fy - 16.0f;
    o.u = 13.0f * o.l * (fx - fy);
    o.v = 13.0f * o.l * (fy - fz);
    return o;
}

__device__ __forceinline__ unsigned pack2(float a, float b) {
    __half2 h = __floats2half2_rn(a, b);
    return *(unsigned*)&h;
}
__device__ __forceinline__ float lo2f(unsigned w) {
    return __low2float(*(__half2*)&w);
}
__device__ __forceinline__ float hi2f(unsigned w) {
    return __high2float(*(__half2*)&w);
}

// Fully fused, 4-rows-per-iteration, interleaved fp16 ring:
//  A: vectorized loads + luv-diff (4 px/thread) -> per-ty sd/s4; read ring olds
//  B: horizontal 15-box via block-sum + increments -> ring (2x STS.128)
//  C: vertical 15-box running sum per column + square + accumulate
__global__ void __launch_bounds__(TPB, 2) fused_kernel(
    const float* __restrict__ in, const float* __restrict__ tgt,
    float* __restrict__ out) {
    extern __shared__ char smraw[];
    uint2* ring = (uint2*)smraw;                         // [RSLOT][W_]
    float* sd   = (float*)(smraw + RING_U2 * 8);         // [4][3][SD_STRIDE]
    float* s4   = sd + 12 * SD_STRIDE;                   // [4][3][S4_STRIDE]

    const int t  = threadIdx.x;
    const int tx = t & 127;
    const int ty = t >> 7;
    const int n     = blockIdx.x >> 4;
    const int strip = blockIdx.x & 15;
    const int h0    = strip * STRIP_H;                   // h0 % 16 == 0

    // Init: zero ring; zero sd/s4 pads (stay zero forever).
    for (int i = t; i < RING_U2; i += TPB) ring[i] = make_uint2(0u, 0u);
    if (t < 240) {
        int p = t / 20, k = t % 20;
        int j = (k < 8) ? k : (512 + k);          // 0..7 or 520..531
        sd[p * SD_STRIDE + j] = 0.f;
    }
    if (t < 48) {
        int p = t / 4, k = t % 4;
        int j = (k < 2) ? k : (128 + k);          // 0,1 or 130,131
        s4[p * S4_STRIDE + j] = 0.f;
    }
    __syncthreads();

    const float4* inA = (const float4*)in;
    const float4* inB = (const float4*)tgt;
    const int P4    = PLANE / 4;                 // 65536
    const int base4 = n * 3 * P4 + tx;
    const int h0m7  = h0 - 7;

    float* sdt = sd + ty * 3 * SD_STRIDE;        // this thread's row buffers
    float* s4t = s4 + ty * 3 * S4_STRIDE;

    float vs0 = 0.f, vs1 = 0.f, vs2 = 0.f;
    float ac0 = 0.f, ac1 = 0.f, ac2 = 0.f;

    #pragma unroll 4
    for (int it = 0; it < ITERS; ++it) {
        const int grel = 4 * it - 8;             // group base row rel. to h0
        const int hr   = h0 + grel + ty;         // this thread's input row

        // ---- phase A: load 4 rows, luv-diff, store sd/s4; read ring olds ----
        float4 d0 = {0.f, 0.f, 0.f, 0.f}, d1 = d0, d2 = d0;
        if ((unsigned)(hr - h0m7) <= 45u && (unsigned)hr < (unsigned)H_) {
            int rb = base4 + hr * (W_ / 4);
            float4 ra = inA[rb], ga = inA[rb + P4], ba = inA[rb + 2 * P4];
            float4 rc = inB[rb], gc = inB[rb + P4], bc = inB[rb + 2 * P4];
            #define LANE(c) { F3 A = rgb2luv(ra.c, ga.c, ba.c); \
                              F3 B = rgb2luv(rc.c, gc.c, bc.c); \
                              d0.c = A.l - B.l; d1.c = A.u - B.u; d2.c = A.v - B.v; }
            LANE(x) LANE(y) LANE(z) LANE(w)
            #undef LANE
        }
        *(float4*)&sdt[8 + 4 * tx]                 = d0;
        *(float4*)&sdt[SD_STRIDE + 8 + 4 * tx]     = d1;
        *(float4*)&sdt[2 * SD_STRIDE + 8 + 4 * tx] = d2;
        s4t[2 + tx]                  = d0.x + d0.y + d0.z + d0.w;
        s4t[S4_STRIDE + 2 + tx]      = d1.x + d1.y + d1.z + d1.w;
        s4t[2 * S4_STRIDE + 2 + tx]  = d2.x + d2.y + d2.z + d2.w;

        // Evicted (old) ring values for rows grel..grel+3: hb[r-15] lives at
        // slot (r+1)&15 and gets overwritten in phase B -> read before barrier.
        uint2 old[4];
        #pragma unroll
        for (int j = 0; j < 4; j++)
            old[j] = ring[((grel + 1 + j) & 15) * W_ + t];
        __syncthreads();

        // ---- phase B: 15-tap hbox for row grel+ty, pixels 4tx..4tx+3 ----
        {
            float hbL[4], hbU[4], hbV[4];
            #pragma unroll
            for (int ch = 0; ch < 3; ch++) {
                const float* sdc = sdt + ch * SD_STRIDE;
                const float* s4c = s4t + ch * S4_STRIDE;
                float s0 = s4c[tx] + s4c[tx + 1] + s4c[tx + 2] + s4c[tx + 3];
                float4 dL = *(const float4*)&sdc[4 * tx];        // d[4tx-8..4tx-5]
                float4 dR = *(const float4*)&sdc[16 + 4 * tx];   // d[4tx+8..4tx+11]
                float* hb = (ch == 0) ? hbL : (ch == 1) ? hbU : hbV;
                hb[0] = s0 - dL.x;
                hb[1] = hb[0] + dR.x - dL.y;
                hb[2] = hb[1] + dR.y - dL.z;
                hb[3] = hb[2] + dR.z - dL.w;
            }
            uint4* wp = (uint4*)(ring + ((grel + ty) & 15) * W_ + 4 * tx);
            uint4 w0, w1;
            w0.x = pack2(hbL[0], hbU[0]); w0.y = pack2(hbV[0], 0.f);
            w0.z = pack2(hbL[1], hbU[1]); w0.w = pack2(hbV[1], 0.f);
            w1.x = pack2(hbL[2], hbU[2]); w1.y = pack2(hbV[2], 0.f);
            w1.z = pack2(hbL[3], hbU[3]); w1.w = pack2(hbV[3], 0.f);
            wp[0] = w0;
            wp[1] = w1;
        }
        __syncthreads();

        // ---- phase C: vertical running sum for column t, 4 new rows ----
        #pragma unroll
        for (int j = 0; j < 4; j++) {
            uint2 nw = ring[((grel + j) & 15) * W_ + t];
            vs0 += lo2f(nw.x) - lo2f(old[j].x);
            vs1 += hi2f(nw.x) - hi2f(old[j].x);
            vs2 += lo2f(nw.y) - lo2f(old[j].y);
            if (grel + j >= 7 && grel + j <= 38) {   // output row (grel+j)-7
                ac0 = fmaf(vs0, vs0, ac0);
                ac1 = fmaf(vs1, vs1, ac1);
                ac2 = fmaf(vs2, vs2, ac2);
            }
        }
    }

    // ---- block reduction ----
    #pragma unroll
    for (int o = 16; o > 0; o >>= 1) {
        ac0 += __shfl_down_sync(0xffffffffu, ac0, o);
        ac1 += __shfl_down_sync(0xffffffffu, ac1, o);
        ac2 += __shfl_down_sync(0xffffffffu, ac2, o);
    }
    __syncthreads();
    float* red = sd;                               // reuse smem
    int wid = t >> 5, lane = t & 31;
    if (lane == 0) { red[wid] = ac0; red[16 + wid] = ac1; red[32 + wid] = ac2; }
    __syncthreads();
    if (t < 3) {
        float s = 0.f;
        #pragma unroll
        for (int i = 0; i < 16; i++) s += red[t * 16 + i];
        atomicAdd(&g_accum[t], (double)s);
    }
    __threadfence();
    __syncthreads();

    // Last block finalizes and resets global state (graph-replay safe).
    __shared__ int is_last;
    if (t == 0) is_last = (atomicAdd(&g_done, 1) == NBLK - 1);
    __syncthreads();
    if (is_last && t == 0) {
        double total = g_accum[0] + g_accum[1] + g_accum[2];
        out[0] = (float)(total / (double)((size_t)N_ * PLANE));
        g_accum[0] = 0.0; g_accum[1] = 0.0; g_accum[2] = 0.0;
        g_done = 0;
    }
}

extern "C" void kernel_launch(void* const* d_in, const int* in_sizes, int n_in,
                              void* d_out, int out_size) {
    const float* in  = (const float*)d_in[0];
    const float* tgt = (const float*)d_in[1];
    float* out = (float*)d_out;

    cudaFuncSetAttribute(fused_kernel,
                         cudaFuncAttributeMaxDynamicSharedMemorySize, SMEM_BYTES);
    fused_kernel<<<NBLK, TPB, SMEM_BYTES>>>(in, tgt, out);
}

// round 7
// speedup vs baseline: 2.4588x; 1.0471x over previous
#include <cuda_runtime.h>
#include <cuda_fp16.h>

// Shape fixed by reference setup: N=16, C=3, H=512, W=512, patch=15.
#define N_       16
#define H_       512
#define W_       512
#define PLANE    (H_ * W_)
#define STRIPS   16
#define STRIP_H  32
#define TPB      512
#define NBLK     (N_ * STRIPS)      // 256
#define ITERS    12                 // 4-row groups covering h0-8 .. h0+39
#define RSLOT    16                 // ring slots (power of 2)
#define SD_STRIDE 532               // 8 pad + 512 + 12 pad
#define S4_STRIDE 132               // 2 pad + 128 + 2 pad
// Ring: [RSLOT][W_] of uint2 {half2(l,u), half2(v,pad)} = 64 KB
#define RING_U2   (RSLOT * W_)
#define SMEM_BYTES (RING_U2 * 8 + 12 * SD_STRIDE * 4 + 12 * S4_STRIDE * 4)

typedef unsigned long long u64;

__device__ double g_accum[3];
__device__ int    g_done = 0;

// ---- packed f32x2 helpers (Blackwell FFMA2/FMUL2 via PTX) ----
__device__ __forceinline__ u64 pk(float lo, float hi) {
    u64 r; asm("mov.b64 %0, {%1,%2};" : "=l"(r) : "f"(lo), "f"(hi)); return r;
}
__device__ __forceinline__ void upk(float& lo, float& hi, u64 v) {
    asm("mov.b64 {%0,%1}, %2;" : "=f"(lo), "=f"(hi) : "l"(v));
}
__device__ __forceinline__ u64 fma2(u64 a, u64 b, u64 c) {
    u64 d; asm("fma.rn.f32x2 %0, %1, %2, %3;" : "=l"(d) : "l"(a), "l"(b), "l"(c));
    return d;
}
__device__ __forceinline__ u64 mul2(u64 a, u64 b) {
    u64 d; asm("mul.rn.f32x2 %0, %1, %2;" : "=l"(d) : "l"(a), "l"(b));
    return d;
}

__device__ __forceinline__ float f_func(float t) {
    // reference: cbrt(t) if t > 0.008856 else 7.787*t + 16/116
    float cb = __powf(t, 1.0f / 3.0f);     // MUFU.LG2 + FMUL + MUFU.EX2
    return (t > 0.008856f) ? cb : fmaf(7.787f, t, 16.0f / 116.0f);
}

__device__ __forceinline__ unsigned pack2h(float a, float b) {
    __half2 h = __floats2half2_rn(a, b);
    return *(unsigned*)&h;
}
__device__ __forceinline__ float lo2f(unsigned w) { return __low2float(*(__half2*)&w); }
__device__ __forceinline__ float hi2f(unsigned w) { return __high2float(*(__half2*)&w); }

// Fully fused, 4-rows-per-iteration, packed-f32x2 luv math:
//  A: clamped vectorized loads + ring-old reads + luv-diff (2 px/instr)
//  B: horizontal 15-box via block-sum + increments -> ring (2x STS.128)
//  C: vertical 15-box running sum per column + square + accumulate
__global__ void __launch_bounds__(TPB, 2) fused_kernel(
    const float* __restrict__ in, const float* __restrict__ tgt,
    float* __restrict__ out) {
    extern __shared__ char smraw[];
    uint2* ring = (uint2*)smraw;                         // [RSLOT][W_]
    float* sd   = (float*)(smraw + RING_U2 * 8);         // [4][3][SD_STRIDE]
    float* s4   = sd + 12 * SD_STRIDE;                   // [4][3][S4_STRIDE]

    const int t  = threadIdx.x;
    const int tx = t & 127;
    const int ty = t >> 7;
    const int n     = blockIdx.x >> 4;
    const int strip = blockIdx.x & 15;
    const int h0    = strip * STRIP_H;                   // h0 % 16 == 0

    // Packed constants (XYZ scales folded into matrix rows 0 and 2).
    #define PC(v) pk((v), (v))
    const u64 K00 = PC(0.4124564f / 0.95047f), K01 = PC(0.3575761f / 0.95047f),
              K02 = PC(0.1804375f / 0.95047f);
    const u64 K10 = PC(0.2126729f), K11 = PC(0.7151522f), K12 = PC(0.0721750f);
    const u64 K20 = PC(0.0193339f / 1.08883f), K21 = PC(0.1191920f / 1.08883f),
              K22 = PC(0.9503041f / 1.08883f);
    const u64 C116 = PC(116.0f), CM16 = PC(-16.0f), C13 = PC(13.0f),
              NEG1 = PC(-1.0f);
    #undef PC

    // luv for a pixel-pair (one image), all math 2-wide except f_func.
    auto luv2 = [&](u64 r, u64 g, u64 b, u64& L, u64& U, u64& V) {
        u64 x = fma2(r, K00, fma2(g, K01, mul2(b, K02)));
        u64 y = fma2(r, K10, fma2(g, K11, mul2(b, K12)));
        u64 z = fma2(r, K20, fma2(g, K21, mul2(b, K22)));
        float x0, x1, y0, y1, z0, z1;
        upk(x0, x1, x); upk(y0, y1, y); upk(z0, z1, z);
        u64 fx = pk(f_func(x0), f_func(x1));
        u64 fy = pk(f_func(y0), f_func(y1));
        u64 fz = pk(f_func(z0), f_func(z1));
        L = fma2(fy, C116, CM16);
        u64 t13 = mul2(L, C13);
        U = mul2(t13, fma2(fy, NEG1, fx));
        V = mul2(t13, fma2(fz, NEG1, fy));
    };

    // Init: zero ring; zero sd/s4 pads (stay zero forever).
    for (int i = t; i < RING_U2; i += TPB) ring[i] = make_uint2(0u, 0u);
    if (t < 240) {
        int p = t / 20, k = t % 20;
        int j = (k < 8) ? k : (512 + k);          // 0..7 or 520..531
        sd[p * SD_STRIDE + j] = 0.f;
    }
    if (t < 48) {
        int p = t / 4, k = t % 4;
        int j = (k < 2) ? k : (128 + k);          // 0,1 or 130,131
        s4[p * S4_STRIDE + j] = 0.f;
    }
    __syncthreads();

    const float4* inA = (const float4*)in;
    const float4* inB = (const float4*)tgt;
    const int P4    = PLANE / 4;                 // 65536
    const int base4 = n * 3 * P4 + tx;
    const int h0m7  = h0 - 7;

    float* sdt = sd + ty * 3 * SD_STRIDE;        // this thread's row buffers
    float* s4t = s4 + ty * 3 * S4_STRIDE;

    float vs0 = 0.f, vs1 = 0.f, vs2 = 0.f;
    float ac0 = 0.f, ac1 = 0.f, ac2 = 0.f;

    #pragma unroll 4
    for (int it = 0; it < ITERS; ++it) {
        const int grel = 4 * it - 8;             // group base row rel. to h0
        const int hr   = h0 + grel + ty;         // this thread's input row

        // ---- phase A: unconditional clamped loads (issue first) ----
        const bool valid = ((unsigned)(hr - h0m7) <= 45u) &&
                           ((unsigned)hr < (unsigned)H_);
        const int hrc = min(max(hr, 0), H_ - 1);
        const int rb  = base4 + hrc * (W_ / 4);
        float4 ra = inA[rb], ga = inA[rb + P4], ba = inA[rb + 2 * P4];
        float4 rc = inB[rb], gc = inB[rb + P4], bc = inB[rb + 2 * P4];

        // Ring olds (consumed in phase C; must be read before phase B writes).
        uint2 old[4];
        #pragma unroll
        for (int j = 0; j < 4; j++)
            old[j] = ring[((grel + 1 + j) & 15) * W_ + t];

        // ---- luv diff, packed 2 px/instr ----
        u64 d0a = 0, d1a = 0, d2a = 0, d0b = 0, d1b = 0, d2b = 0;
        if (valid) {
            u64 lA, uA, vA, lB, uB, vB;
            luv2(pk(ra.x, ra.y), pk(ga.x, ga.y), pk(ba.x, ba.y), lA, uA, vA);
            luv2(pk(rc.x, rc.y), pk(gc.x, gc.y), pk(bc.x, bc.y), lB, uB, vB);
            d0a = fma2(lB, NEG1, lA);
            d1a = fma2(uB, NEG1, uA);
            d2a = fma2(vB, NEG1, vA);
            luv2(pk(ra.z, ra.w), pk(ga.z, ga.w), pk(ba.z, ba.w), lA, uA, vA);
            luv2(pk(rc.z, rc.w), pk(gc.z, gc.w), pk(bc.z, bc.w), lB, uB, vB);
            d0b = fma2(lB, NEG1, lA);
            d1b = fma2(uB, NEG1, uA);
            d2b = fma2(vB, NEG1, vA);
        }
        {
            float4 s;
            upk(s.x, s.y, d0a); upk(s.z, s.w, d0b);
            *(float4*)&sdt[8 + 4 * tx] = s;
            s4t[2 + tx] = (s.x + s.y) + (s.z + s.w);
            upk(s.x, s.y, d1a); upk(s.z, s.w, d1b);
            *(float4*)&sdt[SD_STRIDE + 8 + 4 * tx] = s;
            s4t[S4_STRIDE + 2 + tx] = (s.x + s.y) + (s.z + s.w);
            upk(s.x, s.y, d2a); upk(s.z, s.w, d2b);
            *(float4*)&sdt[2 * SD_STRIDE + 8 + 4 * tx] = s;
            s4t[2 * S4_STRIDE + 2 + tx] = (s.x + s.y) + (s.z + s.w);
        }
        __syncthreads();

        // ---- phase B: 15-tap hbox for row grel+ty, pixels 4tx..4tx+3 ----
        {
            float hbL[4], hbU[4], hbV[4];
            #pragma unroll
            for (int ch = 0; ch < 3; ch++) {
                const float* sdc = sdt + ch * SD_STRIDE;
                const float* s4c = s4t + ch * S4_STRIDE;
                float s0 = s4c[tx] + s4c[tx + 1] + s4c[tx + 2] + s4c[tx + 3];
                float4 dL = *(const float4*)&sdc[4 * tx];        // d[4tx-8..4tx-5]
                float4 dR = *(const float4*)&sdc[16 + 4 * tx];   // d[4tx+8..4tx+11]
                float* hb = (ch == 0) ? hbL : (ch == 1) ? hbU : hbV;
                hb[0] = s0 - dL.x;
                hb[1] = hb[0] + dR.x - dL.y;
                hb[2] = hb[1] + dR.y - dL.z;
                hb[3] = hb[2] + dR.z - dL.w;
            }
            uint4* wp = (uint4*)(ring + ((grel + ty) & 15) * W_ + 4 * tx);
            uint4 w0, w1;
            w0.x = pack2h(hbL[0], hbU[0]); w0.y = pack2h(hbV[0], 0.f);
            w0.z = pack2h(hbL[1], hbU[1]); w0.w = pack2h(hbV[1], 0.f);
            w1.x = pack2h(hbL[2], hbU[2]); w1.y = pack2h(hbV[2], 0.f);
            w1.z = pack2h(hbL[3], hbU[3]); w1.w = pack2h(hbV[3], 0.f);
            wp[0] = w0;
            wp[1] = w1;
        }
        __syncthreads();

        // ---- phase C: vertical running sum for column t, 4 new rows ----
        #pragma unroll
        for (int j = 0; j < 4; j++) {
            uint2 nw = ring[((grel + j) & 15) * W_ + t];
            vs0 += lo2f(nw.x) - lo2f(old[j].x);
            vs1 += hi2f(nw.x) - hi2f(old[j].x);
            vs2 += lo2f(nw.y) - lo2f(old[j].y);
            if (grel + j >= 7 && grel + j <= 38) {   // output row (grel+j)-7
                ac0 = fmaf(vs0, vs0, ac0);
                ac1 = fmaf(vs1, vs1, ac1);
                ac2 = fmaf(vs2, vs2, ac2);
            }
        }
    }

    // ---- block reduction ----
    #pragma unroll
    for (int o = 16; o > 0; o >>= 1) {
        ac0 += __shfl_down_sync(0xffffffffu, ac0, o);
        ac1 += __shfl_down_sync(0xffffffffu, ac1, o);
        ac2 += __shfl_down_sync(0xffffffffu, ac2, o);
    }
    __syncthreads();
    float* red = sd;                               // reuse smem
    int wid = t >> 5, lane = t & 31;
    if (lane == 0) { red[wid] = ac0; red[16 + wid] = ac1; red[32 + wid] = ac2; }
    __syncthreads();
    if (t < 3) {
        float s = 0.f;
        #pragma unroll
        for (int i = 0; i < 16; i++) s += red[t * 16 + i];
        atomicAdd(&g_accum[t], (double)s);
    }
    __threadfence();
    __syncthreads();

    // Last block finalizes and resets global state (graph-replay safe).
    __shared__ int is_last;
    if (t == 0) is_last = (atomicAdd(&g_done, 1) == NBLK - 1);
    __syncthreads();
    if (is_last && t == 0) {
        double total = g_accum[0] + g_accum[1] + g_accum[2];
        out[0] = (float)(total / (double)((size_t)N_ * PLANE));
        g_accum[0] = 0.0; g_accum[1] = 0.0; g_accum[2] = 0.0;
        g_done = 0;
    }
}

extern "C" void kernel_launch(void* const* d_in, const int* in_sizes, int n_in,
                              void* d_out, int out_size) {
    const float* in  = (const float*)d_in[0];
    const float* tgt = (const float*)d_in[1];
    float* out = (float*)d_out;

    cudaFuncSetAttribute(fused_kernel,
                         cudaFuncAttributeMaxDynamicSharedMemorySize, SMEM_BYTES);
    fused_kernel<<<NBLK, TPB, SMEM_BYTES>>>(in, tgt, out);
}